// round 1
// baseline (speedup 1.0000x reference)
#include <cuda_runtime.h>
#include <cstdint>

typedef unsigned long long ull;
#define FULL 0xFFFFFFFFu

constexpr int NUM_GROUP  = 512;
constexpr int GROUP_SIZE = 32;

// ============================================================
// FPS: one block per batch. 1024 threads, points + min_d in regs.
// Packed argmax key: (float_bits(min_d) << 32) | ~idx
//   -> max key = max value, ties -> smallest idx (matches jnp.argmax).
// ============================================================
__global__ __launch_bounds__(1024)
void fps_kernel(const float* __restrict__ xyz, float* __restrict__ centers, int N) {
    const int b   = blockIdx.x;
    const int tid = threadIdx.x;
    const int T   = 1024;

    const float* X = xyz + (size_t)b * 3 * N;
    const float* Y = X + N;
    const float* Z = Y + N;

    // up to 16*1024 = 16384 points supported
    float px[16], py[16], pz[16], md[16];
    const int P = (N + T - 1) / T;
    #pragma unroll
    for (int i = 0; i < 16; i++) {
        if (i < P) {
            int n = tid + i * T;
            bool v = (n < N);
            px[i] = v ? X[n] : 0.f;
            py[i] = v ? Y[n] : 0.f;
            pz[i] = v ? Z[n] : 0.f;
            md[i] = v ? 1e10f : -1.0f;   // invalid slots never win argmax (values >= 0)
        }
    }

    __shared__ ull sbest[2];
    if (tid < 2) sbest[tid] = 0ull;
    __syncthreads();

    float cx = X[0], cy = Y[0], cz = Z[0];
    float* cout = centers + (size_t)b * NUM_GROUP * 3;

    for (int it = 0; it < NUM_GROUP; it++) {
        if (tid == 0) {
            cout[it * 3 + 0] = cx;
            cout[it * 3 + 1] = cy;
            cout[it * 3 + 2] = cz;
        }

        float bv = -1.0f;
        int   bi = 0;
        #pragma unroll
        for (int i = 0; i < 16; i++) {
            if (i < P) {
                float dx = px[i] - cx, dy = py[i] - cy, dz = pz[i] - cz;
                float d  = fmaf(dz, dz, fmaf(dy, dy, dx * dx));
                float m  = fminf(md[i], d);
                // keep invalid slots at -1 (md[i] was -1, d>=0 -> m=-1)
                m = (md[i] < 0.f) ? -1.0f : m;
                md[i] = m;
                if (m > bv) { bv = m; bi = tid + i * T; }   // strict > : first index wins
            }
        }

        ull key = ((ull)__float_as_uint(bv) << 32) | (uint32_t)(~(uint32_t)bi);
        #pragma unroll
        for (int o = 16; o > 0; o >>= 1) {
            ull other = __shfl_xor_sync(FULL, key, o);
            if (other > key) key = other;
        }
        if ((tid & 31) == 0) atomicMax(&sbest[it & 1], key);
        __syncthreads();                         // A: all atomics visible

        ull k   = sbest[it & 1];
        int idx = (int)(~(uint32_t)k);
        if (tid == 0) sbest[(it & 1) ^ 1] = 0ull; // reset slot for it+1 (safe: last read before A of prev iter)
        cx = X[idx]; cy = Y[idx]; cz = Z[idx];    // uniform broadcast LDG (L1 hit)
        __syncthreads();                          // B
    }
}

// ============================================================
// kNN top-32: one warp per group, 8 groups per 256-thread block.
// Block caches the whole batch point cloud in SMEM (3*N floats).
// Warp keeps a lane-sorted ascending list of packed keys
//   key = (float_bits(d2) << 32) | idx   (ties -> lower idx, = lax.top_k)
// Stream 32 candidates/step; insert only candidates beating the kth.
// ============================================================
__global__ __launch_bounds__(256)
void knn_kernel(const float* __restrict__ xyz,
                const float* __restrict__ centers,
                float* __restrict__ nb,
                int N, int blocksPerBatch, int groupsPerBlock) {
    extern __shared__ float s[];
    float* sx = s;
    float* sy = s + N;
    float* sz = s + 2 * N;

    const int b  = blockIdx.x / blocksPerBatch;
    const int g0 = (blockIdx.x % blocksPerBatch) * groupsPerBlock;

    const float* X = xyz + (size_t)b * 3 * N;
    for (int n = threadIdx.x; n < N; n += blockDim.x) {
        sx[n] = X[n];
        sy[n] = X[N + n];
        sz[n] = X[2 * N + n];
    }
    __syncthreads();

    const int warp = threadIdx.x >> 5;
    const int lane = threadIdx.x & 31;
    const int g    = g0 + warp;

    const float* c = centers + ((size_t)b * NUM_GROUP + g) * 3;
    const float cx = c[0], cy = c[1], cz = c[2];

    // --- init with first 32 points, bitonic sort ascending across lanes ---
    ull key;
    {
        float dx = sx[lane] - cx, dy = sy[lane] - cy, dz = sz[lane] - cz;
        float d2 = fmaf(dz, dz, fmaf(dy, dy, dx * dx));
        key = ((ull)__float_as_uint(d2) << 32) | (uint32_t)lane;
    }
    #pragma unroll
    for (int k2 = 2; k2 <= 32; k2 <<= 1) {
        #pragma unroll
        for (int j = k2 >> 1; j > 0; j >>= 1) {
            ull partner = __shfl_xor_sync(FULL, key, j);
            bool lower  = (lane & j) == 0;
            bool asc    = (lane & k2) == 0;
            ull mn = (key < partner) ? key : partner;
            ull mx = (key < partner) ? partner : key;
            key = (lower == asc) ? mn : mx;
        }
    }
    ull kmax = __shfl_sync(FULL, key, 31);

    // --- stream the rest ---
    for (int base = 32; base < N; base += 32) {
        int idx = base + lane;
        float dx = sx[idx] - cx, dy = sy[idx] - cy, dz = sz[idx] - cz;
        float d2 = fmaf(dz, dz, fmaf(dy, dy, dx * dx));
        ull nk = ((ull)__float_as_uint(d2) << 32) | (uint32_t)idx;

        unsigned mask = __ballot_sync(FULL, nk < kmax);
        while (mask) {
            int src = __ffs(mask) - 1;
            mask &= mask - 1;
            ull cand = __shfl_sync(FULL, nk, src);   // uniform broadcast
            if (cand >= kmax) continue;              // kth shrank; uniform branch
            int pos = __popc(__ballot_sync(FULL, key < cand));
            ull up  = __shfl_up_sync(FULL, key, 1);
            if (lane == pos)      key = cand;
            else if (lane > pos)  key = up;
            kmax = __shfl_sync(FULL, key, 31);
        }
    }

    // --- emit: neighborhood = point - center ---
    int idx = (int)(uint32_t)key;
    float ox = sx[idx] - cx, oy = sy[idx] - cy, oz = sz[idx] - cz;
    size_t o = (((size_t)b * NUM_GROUP + g) * GROUP_SIZE + lane) * 3;
    nb[o + 0] = ox;
    nb[o + 1] = oy;
    nb[o + 2] = oz;
}

// ============================================================
extern "C" void kernel_launch(void* const* d_in, const int* in_sizes, int n_in,
                              void* d_out, int out_size) {
    const float* xyz = (const float*)d_in[0];
    float* out = (float*)d_out;

    // out = [B,G,32,3] neighborhood ++ [B,G,3] centers
    const int B = out_size / (NUM_GROUP * (GROUP_SIZE + 1) * 3);
    const int N = in_sizes[0] / (3 * B);

    float* nb      = out;
    float* centers = out + (size_t)B * NUM_GROUP * GROUP_SIZE * 3;

    // FPS: one block per batch
    fps_kernel<<<B, 1024>>>(xyz, centers, N);

    // kNN: 8 groups (warps) per 256-thread block, batch points in SMEM
    const int groupsPerBlock = 8;
    const int blocksPerBatch = NUM_GROUP / groupsPerBlock;
    const size_t smem = (size_t)3 * N * sizeof(float);
    cudaFuncSetAttribute(knn_kernel, cudaFuncAttributeMaxDynamicSharedMemorySize, (int)smem);
    knn_kernel<<<B * blocksPerBatch, 256, smem>>>(xyz, centers, nb, N, blocksPerBatch, groupsPerBlock);
}

// round 2
// speedup vs baseline: 1.7320x; 1.7320x over previous
#include <cuda_runtime.h>
#include <cstdint>

typedef unsigned long long ull;
#define FULL 0xFFFFFFFFu

constexpr int NUM_GROUP  = 512;
constexpr int GROUP_SIZE = 32;
constexpr int TPB        = 1024;   // fused block size
constexpr int MAXB       = 64;

// progress[b] = number of centers published for batch b (monotone within a launch)
__device__ int g_prog[MAXB];

__global__ void init_prog() {
    if (threadIdx.x < MAXB) g_prog[threadIdx.x] = 0;
}

// ---- packed f32x2 helpers (sm_100+) ----
__device__ __forceinline__ ull pack2(float a, float b) {
    ull r; asm("mov.b64 %0,{%1,%2};" : "=l"(r) : "f"(a), "f"(b)); return r;
}
__device__ __forceinline__ void unpack2(ull v, float& a, float& b) {
    asm("mov.b64 {%0,%1},%2;" : "=f"(a), "=f"(b) : "l"(v));
}
__device__ __forceinline__ ull addx2(ull a, ull b) {
    ull r; asm("add.rn.f32x2 %0,%1,%2;" : "=l"(r) : "l"(a), "l"(b)); return r;
}
__device__ __forceinline__ ull mulx2(ull a, ull b) {
    ull r; asm("mul.rn.f32x2 %0,%1,%2;" : "=l"(r) : "l"(a), "l"(b)); return r;
}
__device__ __forceinline__ ull fmax2_(ull a, ull b, ull c) {
    ull r; asm("fma.rn.f32x2 %0,%1,%2,%3;" : "=l"(r) : "l"(a), "l"(b), "l"(c)); return r;
}

// ============================================================
// Fused kernel: blocks [0, B) do FPS (one per batch, exclusive SM),
// blocks [B, B + B*16) do kNN (32 groups per block, one warp each).
// ============================================================
__global__ __launch_bounds__(TPB, 1)
void fused_kernel(const float* __restrict__ xyz,
                  float* __restrict__ nb,
                  float* __restrict__ centers,
                  int N, int B) {
    extern __shared__ float s[];
    const int tid  = threadIdx.x;
    const int lane = tid & 31;
    const int warp = tid >> 5;

    if (blockIdx.x < (unsigned)B) {
        // ==================== FPS ====================
        const int b = blockIdx.x;
        const float* X = xyz + (size_t)b * 3 * N;
        const float* Y = X + N;
        const float* Z = Y + N;

        // up to 8 points (4 f32x2 pairs) per thread: N <= 8192 at TPB=1024
        ull  pxp[4], pyp[4], pzp[4];
        float md[8];
        const int NP = (N + 2 * TPB - 1) / (2 * TPB);   // pairs per thread (4)
        #pragma unroll
        for (int i = 0; i < 4; i++) {
            if (i < NP) {
                int p  = tid + i * TPB;
                int n0 = 2 * p;
                bool v = (n0 + 1 < N) && (n0 >= 0);
                float x0 = v ? X[n0] : 0.f, x1 = v ? X[n0 + 1] : 0.f;
                float y0 = v ? Y[n0] : 0.f, y1 = v ? Y[n0 + 1] : 0.f;
                float z0 = v ? Z[n0] : 0.f, z1 = v ? Z[n0 + 1] : 0.f;
                pxp[i] = pack2(x0, x1);
                pyp[i] = pack2(y0, y1);
                pzp[i] = pack2(z0, z1);
                md[2 * i]     = v ? 1e10f : -1.0f;   // fminf keeps -1 forever (d >= 0)
                md[2 * i + 1] = v ? 1e10f : -1.0f;
            }
        }

        __shared__ ull sb[3];
        if (tid < 3) sb[tid] = 0ull;
        float cx = X[0], cy = Y[0], cz = Z[0];
        float* cout = centers + (size_t)b * NUM_GROUP * 3;
        __syncthreads();

        for (int it = 0; it < NUM_GROUP; it++) {
            if (tid == 0) {
                cout[it * 3 + 0] = cx;
                cout[it * 3 + 1] = cy;
                cout[it * 3 + 2] = cz;
            }
            ull ncx = pack2(-cx, -cx), ncy = pack2(-cy, -cy), ncz = pack2(-cz, -cz);

            #pragma unroll
            for (int i = 0; i < 4; i++) {
                if (i < NP) {
                    ull dx = addx2(pxp[i], ncx);
                    ull dy = addx2(pyp[i], ncy);
                    ull dz = addx2(pzp[i], ncz);
                    ull m  = mulx2(dx, dx);
                    m = fmax2_(dy, dy, m);
                    m = fmax2_(dz, dz, m);     // same rounding as fmaf(dz,dz,fmaf(dy,dy,dx*dx))
                    float d0, d1; unpack2(m, d0, d1);
                    md[2 * i]     = fminf(md[2 * i], d0);
                    md[2 * i + 1] = fminf(md[2 * i + 1], d1);
                }
            }

            // thread-local argmax: max value, then FIRST matching slot (ids ascend with j)
            float bv = md[0];
            #pragma unroll
            for (int j = 1; j < 8; j++) bv = fmaxf(bv, md[j]);
            int bj = 7;
            #pragma unroll
            for (int j = 6; j >= 0; j--) if (md[j] == bv) bj = j;
            int id = 2 * (tid + (bj >> 1) * TPB) + (bj & 1);

            // packed key: max value wins, ties -> smallest global index
            ull key = ((ull)__float_as_uint(bv) << 32) | (uint32_t)(~(uint32_t)id);
            #pragma unroll
            for (int o = 16; o > 0; o >>= 1) {
                ull other = __shfl_xor_sync(FULL, key, o);
                if (other > key) key = other;
            }
            if (lane == 0) atomicMax(&sb[it % 3], key);
            __syncthreads();                      // single barrier per iteration

            ull k   = sb[it % 3];
            int idx = (int)(~(uint32_t)k);
            if (tid == 0) {
                sb[(it + 2) % 3] = 0ull;          // safe: slot idle until iter it+2
                if ((it & 7) == 7) {
                    __threadfence();
                    *(volatile int*)&g_prog[b] = it + 1;   // release-publish centers [0..it]
                }
            }
            cx = X[idx]; cy = Y[idx]; cz = Z[idx];
        }
        if (tid == 0) {
            __threadfence();
            *(volatile int*)&g_prog[b] = NUM_GROUP;
        }
    } else {
        // ==================== kNN top-32 ====================
        const int kb = blockIdx.x - B;
        const int blocksPerBatch = NUM_GROUP / 32;          // 16
        const int b  = kb / blocksPerBatch;
        const int g  = (kb % blocksPerBatch) * 32 + warp;   // this warp's group

        float* sx = s;
        float* sy = s + N;
        float* sz = s + 2 * N;
        const float* X = xyz + (size_t)b * 3 * N;
        for (int n = tid; n < N; n += TPB) {
            sx[n] = X[n];
            sy[n] = X[N + n];
            sz[n] = X[2 * N + n];
        }
        __syncthreads();

        // wait for this group's center (published by the FPS block of batch b)
        if (lane == 0) {
            while (*(volatile int*)&g_prog[b] < g + 1) __nanosleep(1000);
        }
        __syncwarp();
        __threadfence();

        const float* c = centers + ((size_t)b * NUM_GROUP + g) * 3;
        const float cx = __ldcg(&c[0]), cy = __ldcg(&c[1]), cz = __ldcg(&c[2]);

        // init with first 32 points, bitonic sort ascending u64 keys
        ull key;
        {
            float dx = sx[lane] - cx, dy = sy[lane] - cy, dz = sz[lane] - cz;
            float d2 = fmaf(dz, dz, fmaf(dy, dy, dx * dx));
            key = ((ull)__float_as_uint(d2) << 32) | (uint32_t)lane;
        }
        #pragma unroll
        for (int k2 = 2; k2 <= 32; k2 <<= 1) {
            #pragma unroll
            for (int j = k2 >> 1; j > 0; j >>= 1) {
                ull partner = __shfl_xor_sync(FULL, key, j);
                bool lower  = (lane & j) == 0;
                bool asc    = (lane & k2) == 0;
                ull mn = (key < partner) ? key : partner;
                ull mx = (key < partner) ? partner : key;
                key = (lower == asc) ? mn : mx;
            }
        }
        ull kmax = __shfl_sync(FULL, key, 31);

        // scalar step for points [32, 64)
        {
            int idx = 32 + lane;
            float dx = sx[idx] - cx, dy = sy[idx] - cy, dz = sz[idx] - cz;
            float d2 = fmaf(dz, dz, fmaf(dy, dy, dx * dx));
            ull nk = ((ull)__float_as_uint(d2) << 32) | (uint32_t)idx;
            unsigned mask = __ballot_sync(FULL, nk < kmax);
            while (mask) {
                int src = __ffs(mask) - 1;
                mask &= mask - 1;
                ull cand = __shfl_sync(FULL, nk, src);
                if (cand >= kmax) continue;
                int pos = __popc(__ballot_sync(FULL, key < cand));
                ull up  = __shfl_up_sync(FULL, key, 1);
                if (lane == pos)      key = cand;
                else if (lane > pos)  key = up;
                kmax = __shfl_sync(FULL, key, 31);
            }
        }

        // packed stream: 64 candidates per step
        const float2* sx2 = (const float2*)sx;
        const float2* sy2 = (const float2*)sy;
        const float2* sz2 = (const float2*)sz;
        const ull ncx = pack2(-cx, -cx), ncy = pack2(-cy, -cy), ncz = pack2(-cz, -cz);

        for (int base = 64; base < N; base += 64) {
            int h = (base >> 1) + lane;
            float2 xx = sx2[h], yy = sy2[h], zz = sz2[h];
            ull dx = addx2(pack2(xx.x, xx.y), ncx);
            ull dy = addx2(pack2(yy.x, yy.y), ncy);
            ull dz = addx2(pack2(zz.x, zz.y), ncz);
            ull m  = mulx2(dx, dx);
            m = fmax2_(dy, dy, m);
            m = fmax2_(dz, dz, m);
            float d0, d1; unpack2(m, d0, d1);
            int i0 = base + 2 * lane;
            ull k0 = ((ull)__float_as_uint(d0) << 32) | (uint32_t)i0;
            ull k1 = ((ull)__float_as_uint(d1) << 32) | (uint32_t)(i0 + 1);

            unsigned m0 = __ballot_sync(FULL, k0 < kmax);
            unsigned m1 = __ballot_sync(FULL, k1 < kmax);
            while (m0) {
                int src = __ffs(m0) - 1;
                m0 &= m0 - 1;
                ull cand = __shfl_sync(FULL, k0, src);
                if (cand >= kmax) continue;
                int pos = __popc(__ballot_sync(FULL, key < cand));
                ull up  = __shfl_up_sync(FULL, key, 1);
                if (lane == pos)      key = cand;
                else if (lane > pos)  key = up;
                kmax = __shfl_sync(FULL, key, 31);
            }
            while (m1) {
                int src = __ffs(m1) - 1;
                m1 &= m1 - 1;
                ull cand = __shfl_sync(FULL, k1, src);
                if (cand >= kmax) continue;
                int pos = __popc(__ballot_sync(FULL, key < cand));
                ull up  = __shfl_up_sync(FULL, key, 1);
                if (lane == pos)      key = cand;
                else if (lane > pos)  key = up;
                kmax = __shfl_sync(FULL, key, 31);
            }
        }

        // emit: neighborhood = point - center (lane-sorted ascending = top_k order)
        int idx = (int)(uint32_t)key;
        float ox = sx[idx] - cx, oy = sy[idx] - cy, oz = sz[idx] - cz;
        size_t o = (((size_t)b * NUM_GROUP + g) * GROUP_SIZE + lane) * 3;
        nb[o + 0] = ox;
        nb[o + 1] = oy;
        nb[o + 2] = oz;
    }
}

// ============================================================
extern "C" void kernel_launch(void* const* d_in, const int* in_sizes, int n_in,
                              void* d_out, int out_size) {
    const float* xyz = (const float*)d_in[0];
    float* out = (float*)d_out;

    // out = [B,G,32,3] neighborhood ++ [B,G,3] centers
    const int B = out_size / (NUM_GROUP * (GROUP_SIZE + 1) * 3);
    const int N = in_sizes[0] / (3 * B);

    float* nb      = out;
    float* centers = out + (size_t)B * NUM_GROUP * GROUP_SIZE * 3;

    const int knnBlocks = B * (NUM_GROUP / 32);
    const size_t smem = (size_t)3 * N * sizeof(float);

    init_prog<<<1, MAXB>>>();

    cudaFuncSetAttribute(fused_kernel, cudaFuncAttributeMaxDynamicSharedMemorySize, (int)smem);
    fused_kernel<<<B + knnBlocks, TPB, smem>>>(xyz, nb, centers, N, B);
}

// round 3
// speedup vs baseline: 1.9083x; 1.1018x over previous
#include <cuda_runtime.h>
#include <cstdint>

typedef unsigned long long ull;
#define FULL 0xFFFFFFFFu

constexpr int NUM_GROUP  = 512;
constexpr int GROUP_SIZE = 32;
constexpr int TPB        = 512;
constexpr int MAXB       = 64;

// progress[b] = number of centers published for batch b (monotone within a launch)
__device__ int g_prog[MAXB];

__global__ void init_prog() {
    if (threadIdx.x < MAXB) g_prog[threadIdx.x] = 0;
}

// ---- packed f32x2 helpers (sm_100+) ----
__device__ __forceinline__ ull pack2(float a, float b) {
    ull r; asm("mov.b64 %0,{%1,%2};" : "=l"(r) : "f"(a), "f"(b)); return r;
}
__device__ __forceinline__ void unpack2(ull v, float& a, float& b) {
    asm("mov.b64 {%0,%1},%2;" : "=f"(a), "=f"(b) : "l"(v));
}
__device__ __forceinline__ ull addx2(ull a, ull b) {
    ull r; asm("add.rn.f32x2 %0,%1,%2;" : "=l"(r) : "l"(a), "l"(b)); return r;
}
__device__ __forceinline__ ull mulx2(ull a, ull b) {
    ull r; asm("mul.rn.f32x2 %0,%1,%2;" : "=l"(r) : "l"(a), "l"(b)); return r;
}
__device__ __forceinline__ ull fmax2_(ull a, ull b, ull c) {
    ull r; asm("fma.rn.f32x2 %0,%1,%2,%3;" : "=l"(r) : "l"(a), "l"(b), "l"(c)); return r;
}
__device__ __forceinline__ uint32_t redux_max_u32(uint32_t v) {
    uint32_t r; asm("redux.sync.max.u32 %0, %1, 0xffffffff;" : "=r"(r) : "r"(v)); return r;
}
__device__ __forceinline__ uint32_t redux_min_u32(uint32_t v) {
    uint32_t r; asm("redux.sync.min.u32 %0, %1, 0xffffffff;" : "=r"(r) : "r"(v)); return r;
}

// ============================================================
// Fused kernel, TPB=512:
//   blocks [0, B)            : FPS, one per batch (exclusive SM)
//   blocks [B, B + 32*B)     : kNN, 16 groups per block (one warp each)
// ============================================================
__global__ __launch_bounds__(TPB)
void fused_kernel(const float* __restrict__ xyz,
                  float* __restrict__ nb,
                  float* __restrict__ centers,
                  int N, int B) {
    extern __shared__ float s[];
    float* sx = s;
    float* sy = s + N;
    float* sz = s + 2 * N;

    const int tid  = threadIdx.x;
    const int lane = tid & 31;
    const int warp = tid >> 5;

    if (blockIdx.x < (unsigned)B) {
        // ==================== FPS ====================
        const int b = blockIdx.x;
        const float* X = xyz + (size_t)b * 3 * N;
        const float* Y = X + N;
        const float* Z = Y + N;

        // cross-warp argmax table: value (float bits) + id, double buffered.
        // entries [16..31] stay neutral {0, 0xFFFFFFFF} forever.
        __shared__ uint32_t vbuf[2][32];
        __shared__ uint32_t ibuf[2][32];
        if (tid < 64) {
            vbuf[tid >> 5][tid & 31] = 0u;
            ibuf[tid >> 5][tid & 31] = 0xFFFFFFFFu;
        }

        // 8 packed pairs per thread (N <= 8192)
        ull  pxp[8], pyp[8], pzp[8];
        float md[16];
        const int NP = (N + 2 * TPB - 1) / (2 * TPB);
        #pragma unroll
        for (int i = 0; i < 8; i++) {
            if (i < NP) {
                int n0 = 2 * (tid + i * TPB);
                bool v = (n0 + 1 < N);
                float x0 = v ? X[n0] : 0.f, x1 = v ? X[n0 + 1] : 0.f;
                float y0 = v ? Y[n0] : 0.f, y1 = v ? Y[n0 + 1] : 0.f;
                float z0 = v ? Z[n0] : 0.f, z1 = v ? Z[n0 + 1] : 0.f;
                pxp[i] = pack2(x0, x1);
                pyp[i] = pack2(y0, y1);
                pzp[i] = pack2(z0, z1);
                md[2 * i]     = v ? 1e10f : -1.0f;
                md[2 * i + 1] = v ? 1e10f : -1.0f;
            }
        }

        // stage points into smem for fast centroid fetch (LDS)
        for (int n = tid; n < N; n += TPB) {
            sx[n] = X[n]; sy[n] = Y[n]; sz[n] = Z[n];
        }

        float cx = X[0], cy = Y[0], cz = Z[0];
        float* cout = centers + (size_t)b * NUM_GROUP * 3;
        __syncthreads();

        for (int it = 0; it < NUM_GROUP; it++) {
            const int p = it & 1;
            if (tid == 0) {
                cout[it * 3 + 0] = cx;
                cout[it * 3 + 1] = cy;
                cout[it * 3 + 2] = cz;
            }
            ull ncx = pack2(-cx, -cx), ncy = pack2(-cy, -cy), ncz = pack2(-cz, -cz);

            // distance update + incremental argmax (strict > : smallest id wins ties,
            // slot ids ascend with slot number)
            float bv = -2.0f;
            int   bi = 0;
            #pragma unroll
            for (int i = 0; i < 8; i++) {
                if (i < NP) {
                    ull dx = addx2(pxp[i], ncx);
                    ull dy = addx2(pyp[i], ncy);
                    ull dz = addx2(pzp[i], ncz);
                    ull m  = mulx2(dx, dx);
                    m = fmax2_(dy, dy, m);
                    m = fmax2_(dz, dz, m);     // == fmaf(dz,dz,fmaf(dy,dy,dx*dx)) per lane
                    float d0, d1; unpack2(m, d0, d1);
                    float m0 = fminf(md[2 * i],     d0);
                    float m1 = fminf(md[2 * i + 1], d1);
                    md[2 * i]     = m0;
                    md[2 * i + 1] = m1;
                    int base = 2 * (tid + i * TPB);
                    if (m0 > bv) { bv = m0; bi = base; }
                    if (m1 > bv) { bv = m1; bi = base + 1; }
                }
            }

            // warp argmax: max value (float bits monotone for d>=0), min id on ties
            uint32_t fb = __float_as_uint(fmaxf(bv, 0.0f) == bv ? bv : bv); // keep bv as-is
            fb = __float_as_uint(bv);
            uint32_t wmax = redux_max_u32(fb);
            uint32_t q    = (fb == wmax) ? (uint32_t)bi : 0xFFFFFFFFu;
            uint32_t wid  = redux_min_u32(q);
            if (lane == 0) {
                vbuf[p][warp] = wmax;
                ibuf[p][warp] = wid;
            }
            __syncthreads();   // single barrier per iteration

            // every warp redundantly reduces the 32-entry table -> no 2nd barrier
            uint32_t v2 = vbuf[p][lane];
            uint32_t i2 = ibuf[p][lane];
            uint32_t m2 = redux_max_u32(v2);
            uint32_t q2 = (v2 == m2) ? i2 : 0xFFFFFFFFu;
            int idx = (int)redux_min_u32(q2);

            if (tid == 0 && (it & 7) == 7) {
                __threadfence();
                *(volatile int*)&g_prog[b] = it + 1;   // release centers [0..it]
            }
            cx = sx[idx]; cy = sy[idx]; cz = sz[idx];
        }
        if (tid == 0) {
            __threadfence();
            *(volatile int*)&g_prog[b] = NUM_GROUP;
        }
    } else {
        // ==================== kNN top-32 ====================
        const int kb = blockIdx.x - B;
        const int blocksPerBatch = NUM_GROUP / 16;          // 32
        const int b  = kb / blocksPerBatch;
        const int g  = (kb % blocksPerBatch) * 16 + warp;   // this warp's group

        const float* X = xyz + (size_t)b * 3 * N;
        for (int n = tid; n < N; n += TPB) {
            sx[n] = X[n];
            sy[n] = X[N + n];
            sz[n] = X[2 * N + n];
        }
        __syncthreads();

        // wait for this group's center
        if (lane == 0) {
            while (*(volatile int*)&g_prog[b] < g + 1) __nanosleep(256);
        }
        __syncwarp();
        __threadfence();

        const float* c = centers + ((size_t)b * NUM_GROUP + g) * 3;
        const float cx = __ldcg(&c[0]), cy = __ldcg(&c[1]), cz = __ldcg(&c[2]);

        // init with first 32 points, bitonic sort ascending u64 keys
        ull key;
        {
            float dx = sx[lane] - cx, dy = sy[lane] - cy, dz = sz[lane] - cz;
            float d2 = fmaf(dz, dz, fmaf(dy, dy, dx * dx));
            key = ((ull)__float_as_uint(d2) << 32) | (uint32_t)lane;
        }
        #pragma unroll
        for (int k2 = 2; k2 <= 32; k2 <<= 1) {
            #pragma unroll
            for (int j = k2 >> 1; j > 0; j >>= 1) {
                ull partner = __shfl_xor_sync(FULL, key, j);
                bool lower  = (lane & j) == 0;
                bool asc    = (lane & k2) == 0;
                ull mn = (key < partner) ? key : partner;
                ull mx = (key < partner) ? partner : key;
                key = (lower == asc) ? mn : mx;
            }
        }
        ull kmax = __shfl_sync(FULL, key, 31);

        // scalar step for points [32, 64)
        {
            int idx = 32 + lane;
            float dx = sx[idx] - cx, dy = sy[idx] - cy, dz = sz[idx] - cz;
            float d2 = fmaf(dz, dz, fmaf(dy, dy, dx * dx));
            ull nk = ((ull)__float_as_uint(d2) << 32) | (uint32_t)idx;
            unsigned mask = __ballot_sync(FULL, nk < kmax);
            while (mask) {
                int src = __ffs(mask) - 1;
                mask &= mask - 1;
                ull cand = __shfl_sync(FULL, nk, src);
                if (cand >= kmax) continue;
                int pos = __popc(__ballot_sync(FULL, key < cand));
                ull up  = __shfl_up_sync(FULL, key, 1);
                if (lane == pos)      key = cand;
                else if (lane > pos)  key = up;
                kmax = __shfl_sync(FULL, key, 31);
            }
        }

        // packed stream: 64 candidates per step
        const float2* sx2 = (const float2*)sx;
        const float2* sy2 = (const float2*)sy;
        const float2* sz2 = (const float2*)sz;
        const ull ncx = pack2(-cx, -cx), ncy = pack2(-cy, -cy), ncz = pack2(-cz, -cz);

        for (int base = 64; base < N; base += 64) {
            int h = (base >> 1) + lane;
            float2 xx = sx2[h], yy = sy2[h], zz = sz2[h];
            ull dx = addx2(pack2(xx.x, xx.y), ncx);
            ull dy = addx2(pack2(yy.x, yy.y), ncy);
            ull dz = addx2(pack2(zz.x, zz.y), ncz);
            ull m  = mulx2(dx, dx);
            m = fmax2_(dy, dy, m);
            m = fmax2_(dz, dz, m);
            float d0, d1; unpack2(m, d0, d1);
            int i0 = base + 2 * lane;
            ull k0 = ((ull)__float_as_uint(d0) << 32) | (uint32_t)i0;
            ull k1 = ((ull)__float_as_uint(d1) << 32) | (uint32_t)(i0 + 1);

            unsigned m0 = __ballot_sync(FULL, k0 < kmax);
            unsigned m1 = __ballot_sync(FULL, k1 < kmax);
            while (m0) {
                int src = __ffs(m0) - 1;
                m0 &= m0 - 1;
                ull cand = __shfl_sync(FULL, k0, src);
                if (cand >= kmax) continue;
                int pos = __popc(__ballot_sync(FULL, key < cand));
                ull up  = __shfl_up_sync(FULL, key, 1);
                if (lane == pos)      key = cand;
                else if (lane > pos)  key = up;
                kmax = __shfl_sync(FULL, key, 31);
            }
            while (m1) {
                int src = __ffs(m1) - 1;
                m1 &= m1 - 1;
                ull cand = __shfl_sync(FULL, k1, src);
                if (cand >= kmax) continue;
                int pos = __popc(__ballot_sync(FULL, key < cand));
                ull up  = __shfl_up_sync(FULL, key, 1);
                if (lane == pos)      key = cand;
                else if (lane > pos)  key = up;
                kmax = __shfl_sync(FULL, key, 31);
            }
        }

        // emit: neighborhood = point - center (lane-sorted ascending = top_k order)
        int idx = (int)(uint32_t)key;
        float ox = sx[idx] - cx, oy = sy[idx] - cy, oz = sz[idx] - cz;
        size_t o = (((size_t)b * NUM_GROUP + g) * GROUP_SIZE + lane) * 3;
        nb[o + 0] = ox;
        nb[o + 1] = oy;
        nb[o + 2] = oz;
    }
}

// ============================================================
extern "C" void kernel_launch(void* const* d_in, const int* in_sizes, int n_in,
                              void* d_out, int out_size) {
    const float* xyz = (const float*)d_in[0];
    float* out = (float*)d_out;

    // out = [B,G,32,3] neighborhood ++ [B,G,3] centers
    const int B = out_size / (NUM_GROUP * (GROUP_SIZE + 1) * 3);
    const int N = in_sizes[0] / (3 * B);

    float* nb      = out;
    float* centers = out + (size_t)B * NUM_GROUP * GROUP_SIZE * 3;

    const int knnBlocks = B * (NUM_GROUP / 16);
    const size_t smem = (size_t)3 * N * sizeof(float);

    init_prog<<<1, MAXB>>>();

    cudaFuncSetAttribute(fused_kernel, cudaFuncAttributeMaxDynamicSharedMemorySize, (int)smem);
    fused_kernel<<<B + knnBlocks, TPB, smem>>>(xyz, nb, centers, N, B);
}

// round 4
// speedup vs baseline: 1.9469x; 1.0202x over previous
#include <cuda_runtime.h>
#include <cstdint>

typedef unsigned long long ull;
#define FULL 0xFFFFFFFFu

constexpr int NUM_GROUP  = 512;
constexpr int GROUP_SIZE = 32;
constexpr int TPB        = 1024;
constexpr int MAXB       = 64;

// progress[b] = number of centers published for batch b (monotone within a launch)
__device__ int g_prog[MAXB];

__global__ void init_prog() {
    if (threadIdx.x < MAXB) g_prog[threadIdx.x] = 0;
}

// ---- packed f32x2 helpers (sm_100+) ----
__device__ __forceinline__ ull pack2(float a, float b) {
    ull r; asm("mov.b64 %0,{%1,%2};" : "=l"(r) : "f"(a), "f"(b)); return r;
}
__device__ __forceinline__ void unpack2(ull v, float& a, float& b) {
    asm("mov.b64 {%0,%1},%2;" : "=f"(a), "=f"(b) : "l"(v));
}
__device__ __forceinline__ ull addx2(ull a, ull b) {
    ull r; asm("add.rn.f32x2 %0,%1,%2;" : "=l"(r) : "l"(a), "l"(b)); return r;
}
__device__ __forceinline__ ull mulx2(ull a, ull b) {
    ull r; asm("mul.rn.f32x2 %0,%1,%2;" : "=l"(r) : "l"(a), "l"(b)); return r;
}
__device__ __forceinline__ ull fma2_(ull a, ull b, ull c) {
    ull r; asm("fma.rn.f32x2 %0,%1,%2,%3;" : "=l"(r) : "l"(a), "l"(b), "l"(c)); return r;
}
__device__ __forceinline__ uint32_t redux_max_u32(uint32_t v) {
    uint32_t r; asm("redux.sync.max.u32 %0, %1, 0xffffffff;" : "=r"(r) : "r"(v)); return r;
}
__device__ __forceinline__ uint32_t redux_min_u32(uint32_t v) {
    uint32_t r; asm("redux.sync.min.u32 %0, %1, 0xffffffff;" : "=r"(r) : "r"(v)); return r;
}

// ============================================================
// Fused kernel, TPB=1024:
//   blocks [0, B)        : FPS, one per batch (exclusive SM)
//   blocks [B, B + 16*B) : kNN, 32 groups per block (one warp each)
// ============================================================
__global__ __launch_bounds__(TPB, 1)
void fused_kernel(const float* __restrict__ xyz,
                  float* __restrict__ nb,
                  float* __restrict__ centers,
                  int N, int B) {
    extern __shared__ float s[];
    float* sx = s;
    float* sy = s + N;
    float* sz = s + 2 * N;

    const int tid  = threadIdx.x;
    const int lane = tid & 31;
    const int warp = tid >> 5;

    if (blockIdx.x < (unsigned)B) {
        // ==================== FPS ====================
        const int b = blockIdx.x;
        const float* X = xyz + (size_t)b * 3 * N;
        const float* Y = X + N;
        const float* Z = Y + N;

        // cross-warp argmax table (value bits + id), double buffered
        __shared__ uint32_t vbuf[2][32];
        __shared__ uint32_t ibuf[2][32];
        if (tid < 64) {
            vbuf[tid >> 5][tid & 31] = 0u;
            ibuf[tid >> 5][tid & 31] = 0xFFFFFFFFu;
        }

        // 4 packed pairs per thread (N <= 8192)
        ull  pxp[4], pyp[4], pzp[4];
        float md[8];
        const int NP = (N + 2 * TPB - 1) / (2 * TPB);
        float2* sx2w = (float2*)sx;
        float2* sy2w = (float2*)sy;
        float2* sz2w = (float2*)sz;
        #pragma unroll
        for (int i = 0; i < 4; i++) {
            if (i < NP) {
                int p  = tid + i * TPB;
                int n0 = 2 * p;
                bool v = (n0 + 1 < N);
                float x0 = v ? X[n0] : 0.f, x1 = v ? X[n0 + 1] : 0.f;
                float y0 = v ? Y[n0] : 0.f, y1 = v ? Y[n0 + 1] : 0.f;
                float z0 = v ? Z[n0] : 0.f, z1 = v ? Z[n0 + 1] : 0.f;
                pxp[i] = pack2(x0, x1);
                pyp[i] = pack2(y0, y1);
                pzp[i] = pack2(z0, z1);
                md[2 * i]     = v ? 1e10f : -1.0f;
                md[2 * i + 1] = v ? 1e10f : -1.0f;
                // stage to smem from registers (fast centroid fetch later)
                if (v) {
                    sx2w[p] = make_float2(x0, x1);
                    sy2w[p] = make_float2(y0, y1);
                    sz2w[p] = make_float2(z0, z1);
                }
            }
        }

        float cx = X[0], cy = Y[0], cz = Z[0];
        float* cout = centers + (size_t)b * NUM_GROUP * 3;
        __syncthreads();

        for (int it = 0; it < NUM_GROUP; it++) {
            const int p = it & 1;
            if (tid == 0) {
                cout[it * 3 + 0] = cx;
                cout[it * 3 + 1] = cy;
                cout[it * 3 + 2] = cz;
            }
            const ull ncx = pack2(-cx, -cx), ncy = pack2(-cy, -cy), ncz = pack2(-cz, -cz);

            // lean hot loop: 10 instr per 2 points, no argmax bookkeeping
            float bm0 = -2.0f, bm1 = -2.0f;   // two independent max chains
            #pragma unroll
            for (int i = 0; i < 4; i++) {
                if (i < NP) {
                    ull dx = addx2(pxp[i], ncx);
                    ull dy = addx2(pyp[i], ncy);
                    ull dz = addx2(pzp[i], ncz);
                    ull m  = mulx2(dx, dx);
                    m = fma2_(dy, dy, m);
                    m = fma2_(dz, dz, m);      // == fmaf(dz,dz,fmaf(dy,dy,dx*dx)) per lane
                    float d0, d1; unpack2(m, d0, d1);
                    float m0 = fminf(md[2 * i],     d0);
                    float m1 = fminf(md[2 * i + 1], d1);
                    md[2 * i]     = m0;
                    md[2 * i + 1] = m1;
                    bm0 = fmaxf(bm0, m0);
                    bm1 = fmaxf(bm1, m1);
                }
            }
            float bv = fmaxf(bm0, bm1);

            // warp value-max on float bits (guard negatives: bits not monotone)
            uint32_t fb   = (bv >= 0.0f) ? __float_as_uint(bv) : 0u;
            uint32_t wmax = redux_max_u32(fb);

            // deferred index discovery: only candidate threads rescan (rare)
            uint32_t q = 0xFFFFFFFFu;
            if (fb == wmax && bv >= 0.0f) {
                #pragma unroll
                for (int j = 7; j >= 0; j--) {     // descending: keep smallest id
                    if ((j >> 1) < NP && md[j] == bv)
                        q = (uint32_t)(2 * (tid + (j >> 1) * TPB) + (j & 1));
                }
            }
            uint32_t wid = redux_min_u32(q);

            if (lane == 0) {
                vbuf[p][warp] = wmax;
                ibuf[p][warp] = wid;
            }
            __syncthreads();   // single barrier per iteration

            // every warp redundantly reduces the 32-entry table
            uint32_t v2 = vbuf[p][lane];
            uint32_t i2 = ibuf[p][lane];
            uint32_t m2 = redux_max_u32(v2);
            uint32_t q2 = (v2 == m2) ? i2 : 0xFFFFFFFFu;
            int idx = (int)redux_min_u32(q2);

            if (tid == 0 && (it & 7) == 7) {
                __threadfence();
                *(volatile int*)&g_prog[b] = it + 1;   // release centers [0..it]
            }
            cx = sx[idx]; cy = sy[idx]; cz = sz[idx];  // broadcast LDS
        }
        if (tid == 0) {
            __threadfence();
            *(volatile int*)&g_prog[b] = NUM_GROUP;
        }
    } else {
        // ==================== kNN top-32 ====================
        const int kb = blockIdx.x - B;
        const int blocksPerBatch = NUM_GROUP / 32;          // 16
        const int b  = kb / blocksPerBatch;
        const int g  = (kb % blocksPerBatch) * 32 + warp;   // this warp's group

        const float* X = xyz + (size_t)b * 3 * N;
        for (int n = tid; n < N; n += TPB) {
            sx[n] = X[n];
            sy[n] = X[N + n];
            sz[n] = X[2 * N + n];
        }
        __syncthreads();

        // wait for this group's center
        if (lane == 0) {
            while (*(volatile int*)&g_prog[b] < g + 1) __nanosleep(256);
        }
        __syncwarp();
        __threadfence();

        const float* c = centers + ((size_t)b * NUM_GROUP + g) * 3;
        const float cx = __ldcg(&c[0]), cy = __ldcg(&c[1]), cz = __ldcg(&c[2]);

        // init with first 32 points, bitonic sort ascending u64 keys
        ull key;
        {
            float dx = sx[lane] - cx, dy = sy[lane] - cy, dz = sz[lane] - cz;
            float d2 = fmaf(dz, dz, fmaf(dy, dy, dx * dx));
            key = ((ull)__float_as_uint(d2) << 32) | (uint32_t)lane;
        }
        #pragma unroll
        for (int k2 = 2; k2 <= 32; k2 <<= 1) {
            #pragma unroll
            for (int j = k2 >> 1; j > 0; j >>= 1) {
                ull partner = __shfl_xor_sync(FULL, key, j);
                bool lower  = (lane & j) == 0;
                bool asc    = (lane & k2) == 0;
                ull mn = (key < partner) ? key : partner;
                ull mx = (key < partner) ? partner : key;
                key = (lower == asc) ? mn : mx;
            }
        }
        ull kmax = __shfl_sync(FULL, key, 31);

        // scalar step for points [32, 64)
        {
            int idx = 32 + lane;
            float dx = sx[idx] - cx, dy = sy[idx] - cy, dz = sz[idx] - cz;
            float d2 = fmaf(dz, dz, fmaf(dy, dy, dx * dx));
            ull nk = ((ull)__float_as_uint(d2) << 32) | (uint32_t)idx;
            unsigned mask = __ballot_sync(FULL, nk < kmax);
            while (mask) {
                int src = __ffs(mask) - 1;
                mask &= mask - 1;
                ull cand = __shfl_sync(FULL, nk, src);
                if (cand >= kmax) continue;
                int pos = __popc(__ballot_sync(FULL, key < cand));
                ull up  = __shfl_up_sync(FULL, key, 1);
                if (lane == pos)      key = cand;
                else if (lane > pos)  key = up;
                kmax = __shfl_sync(FULL, key, 31);
            }
        }

        // packed stream: 64 candidates per step
        const float2* sx2 = (const float2*)sx;
        const float2* sy2 = (const float2*)sy;
        const float2* sz2 = (const float2*)sz;
        const ull ncx = pack2(-cx, -cx), ncy = pack2(-cy, -cy), ncz = pack2(-cz, -cz);

        for (int base = 64; base < N; base += 64) {
            int h = (base >> 1) + lane;
            float2 xx = sx2[h], yy = sy2[h], zz = sz2[h];
            ull dx = addx2(pack2(xx.x, xx.y), ncx);
            ull dy = addx2(pack2(yy.x, yy.y), ncy);
            ull dz = addx2(pack2(zz.x, zz.y), ncz);
            ull m  = mulx2(dx, dx);
            m = fma2_(dy, dy, m);
            m = fma2_(dz, dz, m);
            float d0, d1; unpack2(m, d0, d1);
            int i0 = base + 2 * lane;
            ull k0 = ((ull)__float_as_uint(d0) << 32) | (uint32_t)i0;
            ull k1 = ((ull)__float_as_uint(d1) << 32) | (uint32_t)(i0 + 1);

            unsigned m0 = __ballot_sync(FULL, k0 < kmax);
            unsigned m1 = __ballot_sync(FULL, k1 < kmax);
            while (m0) {
                int src = __ffs(m0) - 1;
                m0 &= m0 - 1;
                ull cand = __shfl_sync(FULL, k0, src);
                if (cand >= kmax) continue;
                int pos = __popc(__ballot_sync(FULL, key < cand));
                ull up  = __shfl_up_sync(FULL, key, 1);
                if (lane == pos)      key = cand;
                else if (lane > pos)  key = up;
                kmax = __shfl_sync(FULL, key, 31);
            }
            while (m1) {
                int src = __ffs(m1) - 1;
                m1 &= m1 - 1;
                ull cand = __shfl_sync(FULL, k1, src);
                if (cand >= kmax) continue;
                int pos = __popc(__ballot_sync(FULL, key < cand));
                ull up  = __shfl_up_sync(FULL, key, 1);
                if (lane == pos)      key = cand;
                else if (lane > pos)  key = up;
                kmax = __shfl_sync(FULL, key, 31);
            }
        }

        // emit: neighborhood = point - center (lane-sorted ascending = top_k order)
        int idx = (int)(uint32_t)key;
        float ox = sx[idx] - cx, oy = sy[idx] - cy, oz = sz[idx] - cz;
        size_t o = (((size_t)b * NUM_GROUP + g) * GROUP_SIZE + lane) * 3;
        nb[o + 0] = ox;
        nb[o + 1] = oy;
        nb[o + 2] = oz;
    }
}

// ============================================================
extern "C" void kernel_launch(void* const* d_in, const int* in_sizes, int n_in,
                              void* d_out, int out_size) {
    const float* xyz = (const float*)d_in[0];
    float* out = (float*)d_out;

    // out = [B,G,32,3] neighborhood ++ [B,G,3] centers
    const int B = out_size / (NUM_GROUP * (GROUP_SIZE + 1) * 3);
    const int N = in_sizes[0] / (3 * B);

    float* nb      = out;
    float* centers = out + (size_t)B * NUM_GROUP * GROUP_SIZE * 3;

    const int knnBlocks = B * (NUM_GROUP / 32);
    const size_t smem = (size_t)3 * N * sizeof(float);

    init_prog<<<1, MAXB>>>();

    cudaFuncSetAttribute(fused_kernel, cudaFuncAttributeMaxDynamicSharedMemorySize, (int)smem);
    fused_kernel<<<B + knnBlocks, TPB, smem>>>(xyz, nb, centers, N, B);
}

// round 5
// speedup vs baseline: 2.0915x; 1.0743x over previous
#include <cuda_runtime.h>
#include <cstdint>

typedef unsigned long long ull;
#define FULL 0xFFFFFFFFu

constexpr int NUM_GROUP  = 512;
constexpr int GROUP_SIZE = 32;
constexpr int TPB        = 512;
constexpr int MAXB       = 64;

// progress[b] = number of centers published for batch b (monotone within a launch)
__device__ int g_prog[MAXB];

__global__ void init_prog() {
    if (threadIdx.x < MAXB) g_prog[threadIdx.x] = 0;
}

// ---- packed f32x2 helpers (sm_100+) ----
__device__ __forceinline__ ull pack2(float a, float b) {
    ull r; asm("mov.b64 %0,{%1,%2};" : "=l"(r) : "f"(a), "f"(b)); return r;
}
__device__ __forceinline__ void unpack2(ull v, float& a, float& b) {
    asm("mov.b64 {%0,%1},%2;" : "=f"(a), "=f"(b) : "l"(v));
}
__device__ __forceinline__ ull addx2(ull a, ull b) {
    ull r; asm("add.rn.f32x2 %0,%1,%2;" : "=l"(r) : "l"(a), "l"(b)); return r;
}
__device__ __forceinline__ ull mulx2(ull a, ull b) {
    ull r; asm("mul.rn.f32x2 %0,%1,%2;" : "=l"(r) : "l"(a), "l"(b)); return r;
}
__device__ __forceinline__ ull fma2_(ull a, ull b, ull c) {
    ull r; asm("fma.rn.f32x2 %0,%1,%2,%3;" : "=l"(r) : "l"(a), "l"(b), "l"(c)); return r;
}
__device__ __forceinline__ uint32_t redux_max_u32(uint32_t v) {
    uint32_t r; asm("redux.sync.max.u32 %0, %1, 0xffffffff;" : "=r"(r) : "r"(v)); return r;
}
__device__ __forceinline__ uint32_t redux_min_u32(uint32_t v) {
    uint32_t r; asm("redux.sync.min.u32 %0, %1, 0xffffffff;" : "=r"(r) : "r"(v)); return r;
}
__device__ __forceinline__ void st_release_gpu(int* p, int v) {
    asm volatile("st.release.gpu.global.s32 [%0], %1;" :: "l"(p), "r"(v) : "memory");
}
__device__ __forceinline__ int ld_acquire_gpu(const int* p) {
    int v; asm volatile("ld.acquire.gpu.global.s32 %0, [%1];" : "=r"(v) : "l"(p) : "memory");
    return v;
}

// ============================================================
// Fused kernel, TPB=512:
//   blocks [0, B)        : FPS, one per batch (exclusive SM)
//   blocks [B, B + 32*B) : kNN, 16 groups per block (one warp each),
//                          BATCH-MAJOR ordering so early blocks need early groups
// ============================================================
__global__ __launch_bounds__(TPB)
void fused_kernel(const float* __restrict__ xyz,
                  float* __restrict__ nb,
                  float* __restrict__ centers,
                  int N, int B) {
    extern __shared__ float s[];
    float* sx = s;
    float* sy = s + N;
    float* sz = s + 2 * N;

    const int tid  = threadIdx.x;
    const int lane = tid & 31;
    const int warp = tid >> 5;

    if (blockIdx.x < (unsigned)B) {
        // ==================== FPS: 16 points per thread ====================
        const int b = blockIdx.x;
        const float* X = xyz + (size_t)b * 3 * N;
        const float* Y = X + N;
        const float* Z = Y + N;

        // cross-warp argmax table (value bits + id), double buffered.
        // entries [16..31] stay neutral forever.
        __shared__ uint32_t vbuf[2][32];
        __shared__ uint32_t ibuf[2][32];
        if (tid < 64) {
            vbuf[tid >> 5][tid & 31] = 0u;
            ibuf[tid >> 5][tid & 31] = 0xFFFFFFFFu;
        }

        // 8 packed pairs per thread (N <= 8192)
        ull  pxp[8], pyp[8], pzp[8];
        float md[16];
        const int NP = (N + 2 * TPB - 1) / (2 * TPB);
        float2* sx2w = (float2*)sx;
        float2* sy2w = (float2*)sy;
        float2* sz2w = (float2*)sz;
        #pragma unroll
        for (int i = 0; i < 8; i++) {
            if (i < NP) {
                int p  = tid + i * TPB;
                int n0 = 2 * p;
                bool v = (n0 + 1 < N);
                float x0 = v ? X[n0] : 0.f, x1 = v ? X[n0 + 1] : 0.f;
                float y0 = v ? Y[n0] : 0.f, y1 = v ? Y[n0 + 1] : 0.f;
                float z0 = v ? Z[n0] : 0.f, z1 = v ? Z[n0 + 1] : 0.f;
                pxp[i] = pack2(x0, x1);
                pyp[i] = pack2(y0, y1);
                pzp[i] = pack2(z0, z1);
                md[2 * i]     = v ? 1e10f : -1.0f;
                md[2 * i + 1] = v ? 1e10f : -1.0f;
                if (v) {
                    sx2w[p] = make_float2(x0, x1);
                    sy2w[p] = make_float2(y0, y1);
                    sz2w[p] = make_float2(z0, z1);
                }
            }
        }

        float cx = X[0], cy = Y[0], cz = Z[0];
        float* cout = centers + (size_t)b * NUM_GROUP * 3;
        __syncthreads();

        for (int it = 0; it < NUM_GROUP; it++) {
            const int p = it & 1;
            if (tid == 0) {
                cout[it * 3 + 0] = cx;
                cout[it * 3 + 1] = cy;
                cout[it * 3 + 2] = cz;
                if ((it & 3) == 3) st_release_gpu(&g_prog[b], it);  // centers [0..it-1] safe; it stored above, release next time
            }
            const ull ncx = pack2(-cx, -cx), ncy = pack2(-cy, -cy), ncz = pack2(-cz, -cz);

            float bm0 = -2.0f, bm1 = -2.0f;
            #pragma unroll
            for (int i = 0; i < 8; i++) {
                if (i < NP) {
                    ull dx = addx2(pxp[i], ncx);
                    ull dy = addx2(pyp[i], ncy);
                    ull dz = addx2(pzp[i], ncz);
                    ull m  = mulx2(dx, dx);
                    m = fma2_(dy, dy, m);
                    m = fma2_(dz, dz, m);      // == fmaf(dz,dz,fmaf(dy,dy,dx*dx)) per lane
                    float d0, d1; unpack2(m, d0, d1);
                    float m0 = fminf(md[2 * i],     d0);
                    float m1 = fminf(md[2 * i + 1], d1);
                    md[2 * i]     = m0;
                    md[2 * i + 1] = m1;
                    bm0 = fmaxf(bm0, m0);
                    bm1 = fmaxf(bm1, m1);
                }
            }
            float bv = fmaxf(bm0, bm1);

            // warp value-max on float bits (nonneg distances -> bit-monotone)
            uint32_t fb   = (bv >= 0.0f) ? __float_as_uint(bv) : 0u;
            uint32_t wmax = redux_max_u32(fb);

            // deferred index discovery: only candidate threads rescan
            uint32_t q = 0xFFFFFFFFu;
            if (fb == wmax && bv >= 0.0f) {
                #pragma unroll
                for (int j = 15; j >= 0; j--) {          // descending id: smallest wins
                    if ((j >> 1) < NP && md[j] == bv)
                        q = (uint32_t)(2 * (tid + (j >> 1) * TPB) + (j & 1));
                }
            }
            uint32_t wid = redux_min_u32(q);

            if (lane == 0) {
                vbuf[p][warp] = wmax;
                ibuf[p][warp] = wid;
            }
            __syncthreads();   // single barrier per iteration

            uint32_t v2 = vbuf[p][lane];
            uint32_t i2 = ibuf[p][lane];
            uint32_t m2 = redux_max_u32(v2);
            uint32_t q2 = (v2 == m2) ? i2 : 0xFFFFFFFFu;
            int idx = (int)redux_min_u32(q2);

            cx = sx[idx]; cy = sy[idx]; cz = sz[idx];  // broadcast LDS
        }
        if (tid == 0) st_release_gpu(&g_prog[b], NUM_GROUP);
    } else {
        // ==================== kNN top-32 (batch-major block order) ====================
        const int kb    = blockIdx.x - B;
        const int b     = kb % B;                   // batch-major: wave-1 = early groups
        const int chunk = kb / B;
        const int g     = chunk * 16 + warp;        // this warp's group

        const float* X = xyz + (size_t)b * 3 * N;
        const float4* X4 = (const float4*)X;
        float4* sx4 = (float4*)sx;
        float4* sy4 = (float4*)sy;
        float4* sz4 = (float4*)sz;
        const int N4 = N >> 2;
        for (int n = tid; n < N4; n += TPB) {
            sx4[n] = X4[n];
            sy4[n] = X4[N4 + n];
            sz4[n] = X4[2 * N4 + n];
        }
        __syncthreads();

        // wait for this group's center (all lanes poll -> acquire everywhere)
        while (ld_acquire_gpu(&g_prog[b]) < g + 1) __nanosleep(128);

        const float* c = centers + ((size_t)b * NUM_GROUP + g) * 3;
        const float cx = __ldcg(&c[0]), cy = __ldcg(&c[1]), cz = __ldcg(&c[2]);

        // init with first 32 points, bitonic sort ascending u64 keys
        ull key;
        {
            float dx = sx[lane] - cx, dy = sy[lane] - cy, dz = sz[lane] - cz;
            float d2 = fmaf(dz, dz, fmaf(dy, dy, dx * dx));
            key = ((ull)__float_as_uint(d2) << 32) | (uint32_t)lane;
        }
        #pragma unroll
        for (int k2 = 2; k2 <= 32; k2 <<= 1) {
            #pragma unroll
            for (int j = k2 >> 1; j > 0; j >>= 1) {
                ull partner = __shfl_xor_sync(FULL, key, j);
                bool lower  = (lane & j) == 0;
                bool asc    = (lane & k2) == 0;
                ull mn = (key < partner) ? key : partner;
                ull mx = (key < partner) ? partner : key;
                key = (lower == asc) ? mn : mx;
            }
        }
        ull kmax = __shfl_sync(FULL, key, 31);

        // scalar step for points [32, 64)
        {
            int idx = 32 + lane;
            float dx = sx[idx] - cx, dy = sy[idx] - cy, dz = sz[idx] - cz;
            float d2 = fmaf(dz, dz, fmaf(dy, dy, dx * dx));
            ull nk = ((ull)__float_as_uint(d2) << 32) | (uint32_t)idx;
            unsigned mask = __ballot_sync(FULL, nk < kmax);
            while (mask) {
                int src = __ffs(mask) - 1;
                mask &= mask - 1;
                ull cand = __shfl_sync(FULL, nk, src);
                if (cand >= kmax) continue;
                int pos = __popc(__ballot_sync(FULL, key < cand));
                ull up  = __shfl_up_sync(FULL, key, 1);
                if (lane == pos)      key = cand;
                else if (lane > pos)  key = up;
                kmax = __shfl_sync(FULL, key, 31);
            }
        }

        // packed stream: 64 candidates per step
        const float2* sx2 = (const float2*)sx;
        const float2* sy2 = (const float2*)sy;
        const float2* sz2 = (const float2*)sz;
        const ull ncx = pack2(-cx, -cx), ncy = pack2(-cy, -cy), ncz = pack2(-cz, -cz);

        for (int base = 64; base < N; base += 64) {
            int h = (base >> 1) + lane;
            float2 xx = sx2[h], yy = sy2[h], zz = sz2[h];
            ull dx = addx2(pack2(xx.x, xx.y), ncx);
            ull dy = addx2(pack2(yy.x, yy.y), ncy);
            ull dz = addx2(pack2(zz.x, zz.y), ncz);
            ull m  = mulx2(dx, dx);
            m = fma2_(dy, dy, m);
            m = fma2_(dz, dz, m);
            float d0, d1; unpack2(m, d0, d1);
            int i0 = base + 2 * lane;
            ull k0 = ((ull)__float_as_uint(d0) << 32) | (uint32_t)i0;
            ull k1 = ((ull)__float_as_uint(d1) << 32) | (uint32_t)(i0 + 1);

            unsigned m0 = __ballot_sync(FULL, k0 < kmax);
            unsigned m1 = __ballot_sync(FULL, k1 < kmax);
            while (m0) {
                int src = __ffs(m0) - 1;
                m0 &= m0 - 1;
                ull cand = __shfl_sync(FULL, k0, src);
                if (cand >= kmax) continue;
                int pos = __popc(__ballot_sync(FULL, key < cand));
                ull up  = __shfl_up_sync(FULL, key, 1);
                if (lane == pos)      key = cand;
                else if (lane > pos)  key = up;
                kmax = __shfl_sync(FULL, key, 31);
            }
            while (m1) {
                int src = __ffs(m1) - 1;
                m1 &= m1 - 1;
                ull cand = __shfl_sync(FULL, k1, src);
                if (cand >= kmax) continue;
                int pos = __popc(__ballot_sync(FULL, key < cand));
                ull up  = __shfl_up_sync(FULL, key, 1);
                if (lane == pos)      key = cand;
                else if (lane > pos)  key = up;
                kmax = __shfl_sync(FULL, key, 31);
            }
        }

        // emit: neighborhood = point - center (lane-sorted ascending = top_k order)
        int idx = (int)(uint32_t)key;
        float ox = sx[idx] - cx, oy = sy[idx] - cy, oz = sz[idx] - cz;
        size_t o = (((size_t)b * NUM_GROUP + g) * GROUP_SIZE + lane) * 3;
        nb[o + 0] = ox;
        nb[o + 1] = oy;
        nb[o + 2] = oz;
    }
}

// ============================================================
extern "C" void kernel_launch(void* const* d_in, const int* in_sizes, int n_in,
                              void* d_out, int out_size) {
    const float* xyz = (const float*)d_in[0];
    float* out = (float*)d_out;

    // out = [B,G,32,3] neighborhood ++ [B,G,3] centers
    const int B = out_size / (NUM_GROUP * (GROUP_SIZE + 1) * 3);
    const int N = in_sizes[0] / (3 * B);

    float* nb      = out;
    float* centers = out + (size_t)B * NUM_GROUP * GROUP_SIZE * 3;

    const int knnBlocks = B * (NUM_GROUP / 16);
    size_t smem = (size_t)3 * N * sizeof(float);
    if (smem < 120 * 1024) smem = 120 * 1024;   // force 1 block/SM (exclusive FPS SMs)

    init_prog<<<1, MAXB>>>();

    cudaFuncSetAttribute(fused_kernel, cudaFuncAttributeMaxDynamicSharedMemorySize, (int)smem);
    fused_kernel<<<B + knnBlocks, TPB, smem>>>(xyz, nb, centers, N, B);
}

// round 6
// speedup vs baseline: 2.3304x; 1.1142x over previous
#include <cuda_runtime.h>
#include <cstdint>

typedef unsigned long long ull;
#define FULL 0xFFFFFFFFu

constexpr int NUM_GROUP  = 512;
constexpr int GROUP_SIZE = 32;
constexpr int TPB        = 512;
constexpr int MAXB       = 64;

__device__ int g_prog[MAXB];

__global__ void init_prog() {
    if (threadIdx.x < MAXB) g_prog[threadIdx.x] = 0;
}

// ---- packed f32x2 helpers (sm_100+) ----
__device__ __forceinline__ ull pack2(float a, float b) {
    ull r; asm("mov.b64 %0,{%1,%2};" : "=l"(r) : "f"(a), "f"(b)); return r;
}
__device__ __forceinline__ void unpack2(ull v, float& a, float& b) {
    asm("mov.b64 {%0,%1},%2;" : "=f"(a), "=f"(b) : "l"(v));
}
__device__ __forceinline__ ull addx2(ull a, ull b) {
    ull r; asm("add.rn.f32x2 %0,%1,%2;" : "=l"(r) : "l"(a), "l"(b)); return r;
}
__device__ __forceinline__ ull mulx2(ull a, ull b) {
    ull r; asm("mul.rn.f32x2 %0,%1,%2;" : "=l"(r) : "l"(a), "l"(b)); return r;
}
__device__ __forceinline__ ull fma2_(ull a, ull b, ull c) {
    ull r; asm("fma.rn.f32x2 %0,%1,%2,%3;" : "=l"(r) : "l"(a), "l"(b), "l"(c)); return r;
}
__device__ __forceinline__ uint32_t redux_max_u32(uint32_t v) {
    uint32_t r; asm("redux.sync.max.u32 %0, %1, 0xffffffff;" : "=r"(r) : "r"(v)); return r;
}
__device__ __forceinline__ uint32_t redux_min_u32(uint32_t v) {
    uint32_t r; asm("redux.sync.min.u32 %0, %1, 0xffffffff;" : "=r"(r) : "r"(v)); return r;
}
__device__ __forceinline__ void st_release_gpu(int* p, int v) {
    asm volatile("st.release.gpu.global.s32 [%0], %1;" :: "l"(p), "r"(v) : "memory");
}
__device__ __forceinline__ int ld_acquire_gpu(const int* p) {
    int v; asm volatile("ld.acquire.gpu.global.s32 %0, [%1];" : "=r"(v) : "l"(p) : "memory");
    return v;
}

// ============================================================
// Fused kernel, TPB=512:
//   blocks [0, B)        : FPS, one per batch (exclusive SM)
//   blocks [B, B + 32*B) : kNN, 16 groups per block, batch-major order
// ============================================================
__global__ __launch_bounds__(TPB)
void fused_kernel(const float* __restrict__ xyz,
                  float* __restrict__ nb,
                  float* __restrict__ centers,
                  int N, int B) {
    extern __shared__ float s[];
    float* sx = s;
    float* sy = s + N;
    float* sz = s + 2 * N;

    const int tid  = threadIdx.x;
    const int lane = tid & 31;
    const int warp = tid >> 5;

    if (blockIdx.x < (unsigned)B) {
        // ==================== FPS: 16 points per thread ====================
        const int b = blockIdx.x;
        const float* X = xyz + (size_t)b * 3 * N;
        const float* Y = X + N;
        const float* Z = Y + N;

        // value-only cross-warp table, double buffered; lanes [16..31] stay 0
        __shared__ uint32_t vbuf[2][32];
        __shared__ uint32_t idslot[2];
        if (tid < 64) vbuf[tid >> 5][tid & 31] = 0u;
        if (tid < 2)  idslot[tid] = 0xFFFFFFFFu;

        // 8 packed pairs per thread (N <= 8192)
        ull  pxp[8], pyp[8], pzp[8];
        float md[16];
        const int NP = (N + 2 * TPB - 1) / (2 * TPB);
        float2* sx2w = (float2*)sx;
        float2* sy2w = (float2*)sy;
        float2* sz2w = (float2*)sz;
        #pragma unroll
        for (int i = 0; i < 8; i++) {
            if (i < NP) {
                int p  = tid + i * TPB;
                int n0 = 2 * p;
                bool v = (n0 + 1 < N);
                float x0 = v ? X[n0] : 0.f, x1 = v ? X[n0 + 1] : 0.f;
                float y0 = v ? Y[n0] : 0.f, y1 = v ? Y[n0 + 1] : 0.f;
                float z0 = v ? Z[n0] : 0.f, z1 = v ? Z[n0 + 1] : 0.f;
                pxp[i] = pack2(x0, x1);
                pyp[i] = pack2(y0, y1);
                pzp[i] = pack2(z0, z1);
                md[2 * i]     = v ? 1e10f : -1.0f;
                md[2 * i + 1] = v ? 1e10f : -1.0f;
                if (v) {
                    sx2w[p] = make_float2(x0, x1);
                    sy2w[p] = make_float2(y0, y1);
                    sz2w[p] = make_float2(z0, z1);
                }
            }
        }

        float cx = X[0], cy = Y[0], cz = Z[0];
        float* cout = centers + (size_t)b * NUM_GROUP * 3;
        __syncthreads();

        for (int it = 0; it < NUM_GROUP; it++) {
            const int p = it & 1;
            if (tid == 0) {
                cout[it * 3 + 0] = cx;
                cout[it * 3 + 1] = cy;
                cout[it * 3 + 2] = cz;
                // lagged publish: centers [0 .. it-8] long-since stored -> release is cheap
                if ((it & 7) == 7) st_release_gpu(&g_prog[b], it - 7);
            }
            const ull ncx = pack2(-cx, -cx), ncy = pack2(-cy, -cy), ncz = pack2(-cz, -cz);

            // lean hot loop: value-only tracking (10 instr per 2 points)
            float bm0 = -2.0f, bm1 = -2.0f;
            #pragma unroll
            for (int i = 0; i < 8; i++) {
                if (i < NP) {
                    ull dx = addx2(pxp[i], ncx);
                    ull dy = addx2(pyp[i], ncy);
                    ull dz = addx2(pzp[i], ncz);
                    ull m  = mulx2(dx, dx);
                    m = fma2_(dy, dy, m);
                    m = fma2_(dz, dz, m);      // == fmaf(dz,dz,fmaf(dy,dy,dx*dx)) per lane
                    float d0, d1; unpack2(m, d0, d1);
                    float m0 = fminf(md[2 * i],     d0);
                    float m1 = fminf(md[2 * i + 1], d1);
                    md[2 * i]     = m0;
                    md[2 * i + 1] = m1;
                    bm0 = fmaxf(bm0, m0);
                    bm1 = fmaxf(bm1, m1);
                }
            }
            float bv = fmaxf(bm0, bm1);

            // publish warp VALUE only (no index work pre-barrier)
            uint32_t fb   = (bv >= 0.0f) ? __float_as_uint(bv) : 0u;
            uint32_t wmax = redux_max_u32(fb);
            if (lane == 0) vbuf[p][warp] = wmax;
            __syncthreads();                         // bar A

            // all warps: block max from the 16-entry table
            uint32_t v2 = vbuf[p][lane];
            uint32_t m2 = redux_max_u32(v2);
            unsigned tiemask = __ballot_sync(FULL, v2 == m2) & 0xFFFFu;

            // reset the OTHER idslot for use at iteration it+1 (read of it-1 done pre-barA)
            if (tid == TPB - 1) idslot[p ^ 1] = 0xFFFFFFFFu;

            // ONLY winning warp(s) resolve the index (warp-uniform branch)
            if (wmax == m2) {
                uint32_t q = 0xFFFFFFFFu;
                if (fb == m2) {
                    #pragma unroll
                    for (int j = 15; j >= 0; j--) {      // descending id: smallest wins
                        if ((j >> 1) < NP && md[j] == bv)
                            q = (uint32_t)(2 * (tid + (j >> 1) * TPB) + (j & 1));
                    }
                }
                uint32_t idmin = redux_min_u32(q);
                if (lane == 0) {
                    if (__popc(tiemask) == 1) idslot[p] = idmin;           // sole winner
                    else                      atomicMin(&idslot[p], idmin); // exact tie across warps
                }
            }
            __syncthreads();                         // bar B (cheap: tiny middle section)

            int idx = (int)idslot[p];
            cx = sx[idx]; cy = sy[idx]; cz = sz[idx];   // broadcast LDS
        }
        if (tid == 0) st_release_gpu(&g_prog[b], NUM_GROUP);
    } else {
        // ==================== kNN top-32 (batch-major block order) ====================
        const int kb    = blockIdx.x - B;
        const int b     = kb % B;
        const int chunk = kb / B;
        const int g     = chunk * 16 + warp;

        const float* X = xyz + (size_t)b * 3 * N;
        const float4* X4 = (const float4*)X;
        float4* sx4 = (float4*)sx;
        float4* sy4 = (float4*)sy;
        float4* sz4 = (float4*)sz;
        const int N4 = N >> 2;
        for (int n = tid; n < N4; n += TPB) {
            sx4[n] = X4[n];
            sy4[n] = X4[N4 + n];
            sz4[n] = X4[2 * N4 + n];
        }
        __syncthreads();

        while (ld_acquire_gpu(&g_prog[b]) < g + 1) __nanosleep(128);

        const float* c = centers + ((size_t)b * NUM_GROUP + g) * 3;
        const float cx = __ldcg(&c[0]), cy = __ldcg(&c[1]), cz = __ldcg(&c[2]);

        // init with first 32 points, bitonic sort ascending u64 keys
        ull key;
        {
            float dx = sx[lane] - cx, dy = sy[lane] - cy, dz = sz[lane] - cz;
            float d2 = fmaf(dz, dz, fmaf(dy, dy, dx * dx));
            key = ((ull)__float_as_uint(d2) << 32) | (uint32_t)lane;
        }
        #pragma unroll
        for (int k2 = 2; k2 <= 32; k2 <<= 1) {
            #pragma unroll
            for (int j = k2 >> 1; j > 0; j >>= 1) {
                ull partner = __shfl_xor_sync(FULL, key, j);
                bool lower  = (lane & j) == 0;
                bool asc    = (lane & k2) == 0;
                ull mn = (key < partner) ? key : partner;
                ull mx = (key < partner) ? partner : key;
                key = (lower == asc) ? mn : mx;
            }
        }
        ull kmax = __shfl_sync(FULL, key, 31);

        // scalar step for points [32, 64)
        {
            int idx = 32 + lane;
            float dx = sx[idx] - cx, dy = sy[idx] - cy, dz = sz[idx] - cz;
            float d2 = fmaf(dz, dz, fmaf(dy, dy, dx * dx));
            ull nk = ((ull)__float_as_uint(d2) << 32) | (uint32_t)idx;
            unsigned mask = __ballot_sync(FULL, nk < kmax);
            while (mask) {
                int src = __ffs(mask) - 1;
                mask &= mask - 1;
                ull cand = __shfl_sync(FULL, nk, src);
                if (cand >= kmax) continue;
                int pos = __popc(__ballot_sync(FULL, key < cand));
                ull up  = __shfl_up_sync(FULL, key, 1);
                if (lane == pos)      key = cand;
                else if (lane > pos)  key = up;
                kmax = __shfl_sync(FULL, key, 31);
            }
        }

        // packed stream: 64 candidates per step
        const float2* sx2 = (const float2*)sx;
        const float2* sy2 = (const float2*)sy;
        const float2* sz2 = (const float2*)sz;
        const ull ncx = pack2(-cx, -cx), ncy = pack2(-cy, -cy), ncz = pack2(-cz, -cz);

        for (int base = 64; base < N; base += 64) {
            int h = (base >> 1) + lane;
            float2 xx = sx2[h], yy = sy2[h], zz = sz2[h];
            ull dx = addx2(pack2(xx.x, xx.y), ncx);
            ull dy = addx2(pack2(yy.x, yy.y), ncy);
            ull dz = addx2(pack2(zz.x, zz.y), ncz);
            ull m  = mulx2(dx, dx);
            m = fma2_(dy, dy, m);
            m = fma2_(dz, dz, m);
            float d0, d1; unpack2(m, d0, d1);
            int i0 = base + 2 * lane;
            ull k0 = ((ull)__float_as_uint(d0) << 32) | (uint32_t)i0;
            ull k1 = ((ull)__float_as_uint(d1) << 32) | (uint32_t)(i0 + 1);

            unsigned m0 = __ballot_sync(FULL, k0 < kmax);
            unsigned m1 = __ballot_sync(FULL, k1 < kmax);
            while (m0) {
                int src = __ffs(m0) - 1;
                m0 &= m0 - 1;
                ull cand = __shfl_sync(FULL, k0, src);
                if (cand >= kmax) continue;
                int pos = __popc(__ballot_sync(FULL, key < cand));
                ull up  = __shfl_up_sync(FULL, key, 1);
                if (lane == pos)      key = cand;
                else if (lane > pos)  key = up;
                kmax = __shfl_sync(FULL, key, 31);
            }
            while (m1) {
                int src = __ffs(m1) - 1;
                m1 &= m1 - 1;
                ull cand = __shfl_sync(FULL, k1, src);
                if (cand >= kmax) continue;
                int pos = __popc(__ballot_sync(FULL, key < cand));
                ull up  = __shfl_up_sync(FULL, key, 1);
                if (lane == pos)      key = cand;
                else if (lane > pos)  key = up;
                kmax = __shfl_sync(FULL, key, 31);
            }
        }

        // emit: neighborhood = point - center (lane-sorted ascending = top_k order)
        int idx = (int)(uint32_t)key;
        float ox = sx[idx] - cx, oy = sy[idx] - cy, oz = sz[idx] - cz;
        size_t o = (((size_t)b * NUM_GROUP + g) * GROUP_SIZE + lane) * 3;
        nb[o + 0] = ox;
        nb[o + 1] = oy;
        nb[o + 2] = oz;
    }
}

// ============================================================
extern "C" void kernel_launch(void* const* d_in, const int* in_sizes, int n_in,
                              void* d_out, int out_size) {
    const float* xyz = (const float*)d_in[0];
    float* out = (float*)d_out;

    const int B = out_size / (NUM_GROUP * (GROUP_SIZE + 1) * 3);
    const int N = in_sizes[0] / (3 * B);

    float* nb      = out;
    float* centers = out + (size_t)B * NUM_GROUP * GROUP_SIZE * 3;

    const int knnBlocks = B * (NUM_GROUP / 16);
    size_t smem = (size_t)3 * N * sizeof(float);
    if (smem < 120 * 1024) smem = 120 * 1024;   // force 1 block/SM

    init_prog<<<1, MAXB>>>();

    cudaFuncSetAttribute(fused_kernel, cudaFuncAttributeMaxDynamicSharedMemorySize, (int)smem);
    fused_kernel<<<B + knnBlocks, TPB, smem>>>(xyz, nb, centers, N, B);
}